// round 10
// baseline (speedup 1.0000x reference)
#include <cuda_runtime.h>
#include <math.h>

// ---------------------------------------------------------------------------
// CReST loss, 7 launches:
//   1. k_rows         : wu rows (maxp, confident-list) + x rows (CE); packed
//                       f32x2 sum-of-exp, scalar fmax tracking (no argmax)
//   2. k_argmax       : first-index argmax, only for confident rows (~6%)
//   3. k_seghist_rank : per-segment class counts + within-segment stable rank
//   4. k_scan         : per-class exclusive scan over segments + bn
//   5. k_compact      : build active-row list (rebal mask)
//   6. k_su           : unsupervised CE for active rows only
//   7. k_reduce       : deterministic final reduction
//   out[0]=loss, out[1]=Lx, out[2]=Lu, out[3..3+N)=max_probs
// ---------------------------------------------------------------------------

#define FULLMASK 0xffffffffu
#define MAXC 1024
#define SEG 256
#define MAXN 65536
#define NSEG_MAX (MAXN / SEG)
#define MAXBX 32768
#define WPB 8
#define L2E 1.4426950408889634f

__device__ int           g_tm[MAXN];
__device__ unsigned char g_local[MAXN];
__device__ float         g_ce_x[MAXBX];
__device__ float         g_ce_u[MAXN];
__device__ int           g_seg_counts[NSEG_MAX][MAXC];
__device__ int           g_seg_off[NSEG_MAX][MAXC];
__device__ int           g_bn[MAXC];
__device__ int           g_clist[MAXN];      // confident rows (pass B worklist)
__device__ int           g_alist[MAXN];      // active rows for k_su
__device__ unsigned int  g_nconf = 0;        // reset by k_seghist_rank
__device__ unsigned int  g_nact  = 0;        // reset by k_scan

// ---- packed f32x2 helpers ---------------------------------------------------
typedef unsigned long long ull;

__device__ __forceinline__ ull pack2(float lo, float hi) {
    ull r; asm("mov.b64 %0, {%1, %2};" : "=l"(r) : "f"(lo), "f"(hi)); return r;
}
__device__ __forceinline__ void unpack2(ull p, float& lo, float& hi) {
    asm("mov.b64 {%0, %1}, %2;" : "=f"(lo), "=f"(hi) : "l"(p));
}
__device__ __forceinline__ ull mul2(ull a, ull b) {
    ull d; asm("mul.rn.f32x2 %0, %1, %2;" : "=l"(d) : "l"(a), "l"(b)); return d;
}
__device__ __forceinline__ ull add2(ull a, ull b) {
    ull d; asm("add.rn.f32x2 %0, %1, %2;" : "=l"(d) : "l"(a), "l"(b)); return d;
}
__device__ __forceinline__ ull ex2_2(ull a) {  // exp2 on both halves
    ull d;
    asm("{ .reg .f32 x, y;\n\t"
        "mov.b64 {x, y}, %1;\n\t"
        "ex2.approx.f32 x, x;\n\t"
        "ex2.approx.f32 y, y;\n\t"
        "mov.b64 %0, {x, y}; }" : "=l"(d) : "l"(a));
    return d;
}
__device__ __forceinline__ float ex2_1(float x) {
    float d; asm("ex2.approx.f32 %0, %1;" : "=f"(d) : "f"(x)); return d;
}

// ---- 1: fused wu (maxp + confident list) and x (supervised CE) rows ---------
__global__ void __launch_bounds__(WPB * 32, 8)
k_rows(const float* __restrict__ lwu,
       const float* __restrict__ lx,
       const int* __restrict__ tgts,
       int C, int N, int Bx,
       float* __restrict__ maxp_out) {
    int lane = threadIdx.x & 31;
    int gw = blockIdx.x * WPB + (threadIdx.x >> 5);
    int n4 = C >> 2;
    int tail = C & 3;
    const ull kL2E2 = pack2(L2E, L2E);

    if (gw < N) {
        // ---- weak-aug row: packed sum-of-exp + scalar max (no index) ----
        const float* rowp = lwu + (size_t)gw * C;
        const float4* rp = (const float4*)rowp;

        ull acc01 = 0, acc23 = 0;                       // (0.f, 0.f) packed
        float m = -INFINITY;
        #pragma unroll
        for (int u = 0; u < 8; u++) {
            int k = lane + u * 32;
            if (k < n4) {
                float4 c = __ldcs(rp + k);
                // FMNMX runs on the alu pipe; f32x2 mul/add on the fma pipe
                m = fmaxf(m, fmaxf(fmaxf(c.x, c.y), fmaxf(c.z, c.w)));
                acc01 = add2(acc01, ex2_2(mul2(pack2(c.x, c.y), kL2E2)));
                acc23 = add2(acc23, ex2_2(mul2(pack2(c.z, c.w), kL2E2)));
            }
        }
        float s;
        {
            float a, b;
            unpack2(add2(acc01, acc23), a, b);
            s = a + b;
        }
        if (tail && lane < tail) {
            float tv = __ldcs(rowp + 4 * n4 + lane);
            m = fmaxf(m, tv);
            s += ex2_1(tv * L2E);
        }

        #pragma unroll
        for (int o = 16; o; o >>= 1) {
            m = fmaxf(m, __shfl_xor_sync(FULLMASK, m, o));
            s += __shfl_xor_sync(FULLMASK, s, o);
        }

        if (lane == 0) {
            float maxp = ex2_1(m * L2E) / s;
            maxp_out[gw] = maxp;
            g_tm[gw] = 0;                       // pass B overwrites if confident
            if (maxp >= 0.95f) {
                unsigned int p = atomicAdd(&g_nconf, 1u);
                g_clist[p] = gw;
            }
        }
    } else if (gw < N + Bx) {
        // ---- supervised row: packed sum-of-exp; target loaded directly ----
        int row = gw - N;
        const float* rowp = lx + (size_t)row * C;
        const float4* rp = (const float4*)rowp;
        float tval = __ldg(rowp + tgts[row]);   // broadcast load per warp

        ull acc01 = 0, acc23 = 0;
        #pragma unroll
        for (int u = 0; u < 8; u++) {
            int k = lane + u * 32;
            if (k < n4) {
                float4 c = __ldcs(rp + k);
                acc01 = add2(acc01, ex2_2(mul2(pack2(c.x, c.y), kL2E2)));
                acc23 = add2(acc23, ex2_2(mul2(pack2(c.z, c.w), kL2E2)));
            }
        }
        float s;
        {
            float a, b;
            unpack2(add2(acc01, acc23), a, b);
            s = a + b;
        }
        if (tail && lane < tail)
            s += ex2_1(__ldcs(rowp + 4 * n4 + lane) * L2E);

        #pragma unroll
        for (int o = 16; o; o >>= 1) s += __shfl_xor_sync(FULLMASK, s, o);

        if (lane == 0)
            g_ce_x[row] = logf(s) - tval;
    }
}

// ---- 2: first-index argmax for confident rows only --------------------------
__global__ void __launch_bounds__(WPB * 32, 8)
k_argmax(const float* __restrict__ lwu, int C) {
    int lane = threadIdx.x & 31;
    int w = blockIdx.x * WPB + (threadIdx.x >> 5);
    if (w >= (int)g_nconf) return;        // one broadcast load, then exit
    int row = g_clist[w];

    const float* rowp = lwu + (size_t)row * C;
    const float4* rp = (const float4*)rowp;
    int n4 = C >> 2;
    int tail = C & 3;

    float m = -INFINITY;
    int bi = 0x3fffffff;
    #pragma unroll
    for (int u = 0; u < 8; u++) {
        int k = lane + u * 32;
        if (k < n4) {
            float4 c = rp[k];
            int j = 4 * k;
            if (c.x > m) { m = c.x; bi = j; }
            if (c.y > m) { m = c.y; bi = j + 1; }
            if (c.z > m) { m = c.z; bi = j + 2; }
            if (c.w > m) { m = c.w; bi = j + 3; }
        }
    }
    if (tail && lane < tail) {
        int j = 4 * n4 + lane;
        float tv = rowp[j];
        if (tv > m) { m = tv; bi = j; }
    }
    #pragma unroll
    for (int o = 16; o; o >>= 1) {
        float om = __shfl_xor_sync(FULLMASK, m, o);
        int   oi = __shfl_xor_sync(FULLMASK, bi, o);
        if (om > m || (om == m && oi < bi)) { m = om; bi = oi; }
    }
    if (lane == 0) g_tm[row] = bi;
}

// ---- 3: per-segment class counts + within-segment stable rank ---------------
__global__ void k_seghist_rank(int N, int C) {
    __shared__ unsigned char whist[WPB][MAXC];
    int r = threadIdx.x;
    int w = r >> 5;
    int lane = r & 31;
    int row = blockIdx.x * SEG + r;

    if (blockIdx.x == 0 && r == 0) g_nconf = 0;   // reset for next replay

    unsigned int* hz = (unsigned int*)whist;
    #pragma unroll
    for (int i = r; i < WPB * MAXC / 4; i += SEG) hz[i] = 0u;

    int myc = (row < N) ? g_tm[row] : -1;

    unsigned int mmask = __match_any_sync(FULLMASK, myc);
    int within = __popc(mmask & ((1u << lane) - 1u));
    int leader = __ffs(mmask) - 1;

    __syncthreads();
    if (lane == leader && myc >= 0)
        whist[w][myc] = (unsigned char)__popc(mmask);
    __syncthreads();

    if (row < N) {
        int cross = 0;
        #pragma unroll
        for (int j = 0; j < WPB; j++)
            if (j < w) cross += whist[j][myc];
        g_local[row] = (unsigned char)(cross + within);
    }

    for (int c = r; c < C; c += SEG) {
        int cnt = 0;
        #pragma unroll
        for (int j = 0; j < WPB; j++) cnt += whist[j][c];
        g_seg_counts[blockIdx.x][c] = cnt;
    }
}

// ---- 4: per-class exclusive scan over segments + bn -------------------------
__global__ void k_scan(int nseg, const float* __restrict__ gtp) {
    int c = blockIdx.x;
    int s = threadIdx.x;
    int lane = s & 31, w = s >> 5;

    if (c == 0 && s == 0) g_nact = 0;    // reset before k_compact fills it

    int v = (s < nseg) ? g_seg_counts[s][c] : 0;

    int x = v;
    #pragma unroll
    for (int o = 1; o < 32; o <<= 1) {
        int t = __shfl_up_sync(FULLMASK, x, o);
        if (lane >= o) x += t;
    }

    __shared__ int wsum[8];
    __shared__ int woff[8];
    if (lane == 31) wsum[w] = x;
    __syncthreads();
    if (w == 0) {
        int y = (lane < 8) ? wsum[lane] : 0;
        #pragma unroll
        for (int o = 1; o < 8; o <<= 1) {
            int t = __shfl_up_sync(FULLMASK, y, o);
            if (lane >= o) y += t;
        }
        if (lane < 8) woff[lane] = y;
    }
    __syncthreads();

    int incl = x + (w ? woff[w - 1] : 0);
    if (s < nseg) g_seg_off[s][c] = incl - v;
    if (s == SEG - 1) {
        // round half-to-even, matching jnp.round
        g_bn[c] = (int)rintf((float)incl * gtp[c]);
    }
}

// ---- 5: build active-row list (rebal mask) ----------------------------------
__global__ void k_compact(int N) {
    int row = blockIdx.x * SEG + threadIdx.x;
    if (row >= N) return;
    int tgt = g_tm[row];
    bool active = false;
    if (tgt != 0) {
        int rank = g_seg_off[row >> 8][tgt] + (int)g_local[row];
        active = (rank < g_bn[tgt]);
    }
    if (active) {
        unsigned int p = atomicAdd(&g_nact, 1u);
        g_alist[p] = row;
    } else {
        g_ce_u[row] = 0.f;
    }
}

// ---- 6: unsupervised CE for active rows only --------------------------------
__global__ void __launch_bounds__(WPB * 32, 8)
k_su(const float* __restrict__ lsu, int C) {
    int lane = threadIdx.x & 31;
    int w = blockIdx.x * WPB + (threadIdx.x >> 5);
    if (w >= (int)g_nact) return;        // one broadcast load, then exit
    int row = g_alist[w];
    int tgt = g_tm[row];

    const float* rowp = lsu + (size_t)row * C;
    const float4* rp = (const float4*)rowp;
    int n4 = C >> 2;
    int tail = C & 3;
    const ull kL2E2 = pack2(L2E, L2E);
    float tval = __ldg(rowp + tgt);

    ull acc01 = 0, acc23 = 0;
    #pragma unroll
    for (int u = 0; u < 8; u++) {
        int k = lane + u * 32;
        if (k < n4) {
            float4 c = __ldcs(rp + k);
            acc01 = add2(acc01, ex2_2(mul2(pack2(c.x, c.y), kL2E2)));
            acc23 = add2(acc23, ex2_2(mul2(pack2(c.z, c.w), kL2E2)));
        }
    }
    float s;
    {
        float a, b;
        unpack2(add2(acc01, acc23), a, b);
        s = a + b;
    }
    if (tail && lane < tail)
        s += ex2_1(__ldcs(rowp + 4 * n4 + lane) * L2E);

    #pragma unroll
    for (int o = 16; o; o >>= 1) s += __shfl_xor_sync(FULLMASK, s, o);

    if (lane == 0)
        g_ce_u[row] = logf(s) - tval;
}

// ---- 7: deterministic final reduction ---------------------------------------
__global__ void k_reduce(int Bx, int N, float* __restrict__ out) {
    __shared__ float sh[1024];
    __shared__ float lx_s;
    int tid = threadIdx.x;

    float a = 0.f;
    for (int i = tid; i < Bx; i += 1024) a += g_ce_x[i];
    sh[tid] = a;
    __syncthreads();
    for (int o = 512; o; o >>= 1) {
        if (tid < o) sh[tid] += sh[tid + o];
        __syncthreads();
    }
    if (tid == 0) lx_s = sh[0];
    __syncthreads();

    float b = 0.f;
    for (int i = tid; i < N; i += 1024) b += g_ce_u[i];
    sh[tid] = b;
    __syncthreads();
    for (int o = 512; o; o >>= 1) {
        if (tid < o) sh[tid] += sh[tid + o];
        __syncthreads();
    }
    if (tid == 0) {
        float Lx = lx_s / (float)Bx;
        float Lu = sh[0] / (float)N;
        out[0] = Lx + Lu;  // LAMBDA_U = 1.0
        out[1] = Lx;
        out[2] = Lu;
    }
}

// ---------------------------------------------------------------------------
extern "C" void kernel_launch(void* const* d_in, const int* in_sizes, int n_in,
                              void* d_out, int out_size) {
    const float* lx  = (const float*)d_in[0];
    const float* lwu = (const float*)d_in[1];
    const float* lsu = (const float*)d_in[2];
    const int*   tx  = (const int*)d_in[3];
    const float* gtp = (const float*)d_in[4];
    // d_in[5] = t (unused)

    int Bx = in_sizes[3];
    int C  = in_sizes[4];
    int N  = in_sizes[1] / C;
    int nseg = (N + SEG - 1) / SEG;

    float* out = (float*)d_out;

    int rows = N + Bx;
    int blk_rows = (rows + WPB - 1) / WPB;
    int blk_n    = (N + WPB - 1) / WPB;

    k_rows<<<blk_rows, WPB * 32>>>(lwu, lx, tx, C, N, Bx, out + 3);   // 1
    k_argmax<<<blk_n, WPB * 32>>>(lwu, C);                            // 2
    k_seghist_rank<<<nseg, SEG>>>(N, C);                              // 3
    k_scan<<<C, SEG>>>(nseg, gtp);                                    // 4
    k_compact<<<nseg, SEG>>>(N);                                      // 5
    k_su<<<blk_n, WPB * 32>>>(lsu, C);                                // 6
    k_reduce<<<1, 1024>>>(Bx, N, out);                                // 7
}

// round 11
// speedup vs baseline: 1.0496x; 1.0496x over previous
#include <cuda_runtime.h>
#include <math.h>

// ---------------------------------------------------------------------------
// CReST loss, 6 launches:
//   1. k_rows    : wu rows (maxp + t_m, inline argmax) + x rows (CE)
//   2. k_seghist_rank : per-segment class counts (transposed) + stable rank
//   3. k_scan    : per-class exclusive scan over segments + bn (coalesced)
//   4. k_compact : build active-row list (rebal mask)
//   5. k_su      : unsupervised CE for active rows only
//   6. k_reduce  : deterministic final reduction
//   out[0]=loss, out[1]=Lx, out[2]=Lu, out[3..3+N)=max_probs
// ---------------------------------------------------------------------------

#define FULLMASK 0xffffffffu
#define MAXC 1024
#define SEG 256
#define MAXN 65536
#define NSEG_MAX (MAXN / SEG)
#define MAXBX 32768
#define WPB 8
#define L2E 1.4426950408889634f

__device__ int           g_tm[MAXN];
__device__ unsigned char g_local[MAXN];
__device__ float         g_ce_x[MAXBX];
__device__ float         g_ce_u[MAXN];
__device__ int           g_seg_counts_t[MAXC][NSEG_MAX];  // [class][segment]
__device__ int           g_seg_off[NSEG_MAX][MAXC];
__device__ int           g_bn[MAXC];
__device__ int           g_alist[MAXN];      // active rows for k_su
__device__ unsigned int  g_nact = 0;         // reset by k_scan

// ---- 1: fused wu (maxp + t_m) and x (supervised CE) rows --------------------
__global__ void __launch_bounds__(WPB * 32, 8)
k_rows(const float* __restrict__ lwu,
       const float* __restrict__ lx,
       const int* __restrict__ tgts,
       int C, int N, int Bx,
       float* __restrict__ maxp_out) {
    int lane = threadIdx.x & 31;
    int gw = blockIdx.x * WPB + (threadIdx.x >> 5);
    int n4 = C >> 2;
    int tail = C & 3;

    if (gw < N) {
        // ---- weak-aug row: sum-of-exp + inline first-index argmax ----
        const float* rowp = lwu + (size_t)gw * C;
        const float4* rp = (const float4*)rowp;

        float m = -INFINITY;
        int bi = 0x3fffffff;
        float s0 = 0.f, s1 = 0.f;
        #pragma unroll
        for (int u = 0; u < 8; u++) {
            int k = lane + u * 32;
            if (k < n4) {
                float4 c = __ldcs(rp + k);
                int j = 4 * k;
                if (c.x > m) { m = c.x; bi = j; }
                if (c.y > m) { m = c.y; bi = j + 1; }
                if (c.z > m) { m = c.z; bi = j + 2; }
                if (c.w > m) { m = c.w; bi = j + 3; }
                s0 += exp2f(c.x * L2E) + exp2f(c.y * L2E);
                s1 += exp2f(c.z * L2E) + exp2f(c.w * L2E);
            }
        }
        if (tail && lane < tail) {
            int j = 4 * n4 + lane;
            float tv = __ldcs(rowp + j);
            if (tv > m) { m = tv; bi = j; }
            s0 += exp2f(tv * L2E);
        }
        float s = s0 + s1;

        #pragma unroll
        for (int o = 16; o; o >>= 1) {
            float om = __shfl_xor_sync(FULLMASK, m, o);
            int   oi = __shfl_xor_sync(FULLMASK, bi, o);
            s += __shfl_xor_sync(FULLMASK, s, o);
            if (om > m || (om == m && oi < bi)) { m = om; bi = oi; }
        }

        if (lane == 0) {
            float maxp = exp2f(m * L2E) / s;
            maxp_out[gw] = maxp;
            g_tm[gw] = (maxp >= 0.95f) ? bi : 0;
        }
    } else if (gw < N + Bx) {
        // ---- supervised row: sum-of-exp; target via broadcast load ----
        int row = gw - N;
        const float* rowp = lx + (size_t)row * C;
        const float4* rp = (const float4*)rowp;
        float tval = __ldg(rowp + tgts[row]);

        float s0 = 0.f, s1 = 0.f;
        #pragma unroll
        for (int u = 0; u < 8; u++) {
            int k = lane + u * 32;
            if (k < n4) {
                float4 c = __ldcs(rp + k);
                s0 += exp2f(c.x * L2E) + exp2f(c.y * L2E);
                s1 += exp2f(c.z * L2E) + exp2f(c.w * L2E);
            }
        }
        if (tail && lane < tail)
            s0 += exp2f(__ldcs(rowp + 4 * n4 + lane) * L2E);
        float s = s0 + s1;

        #pragma unroll
        for (int o = 16; o; o >>= 1) s += __shfl_xor_sync(FULLMASK, s, o);

        if (lane == 0)
            g_ce_x[row] = logf(s) - tval;
    }
}

// ---- 2: per-segment class counts (transposed) + within-segment stable rank --
__global__ void k_seghist_rank(int N, int C) {
    __shared__ unsigned char whist[WPB][MAXC];
    int r = threadIdx.x;
    int w = r >> 5;
    int lane = r & 31;
    int row = blockIdx.x * SEG + r;

    unsigned int* hz = (unsigned int*)whist;
    #pragma unroll
    for (int i = r; i < WPB * MAXC / 4; i += SEG) hz[i] = 0u;

    int myc = (row < N) ? g_tm[row] : -1;

    unsigned int mmask = __match_any_sync(FULLMASK, myc);
    int within = __popc(mmask & ((1u << lane) - 1u));
    int leader = __ffs(mmask) - 1;

    __syncthreads();
    if (lane == leader && myc >= 0)
        whist[w][myc] = (unsigned char)__popc(mmask);
    __syncthreads();

    if (row < N) {
        int cross = 0;
        #pragma unroll
        for (int j = 0; j < WPB; j++)
            if (j < w) cross += whist[j][myc];
        g_local[row] = (unsigned char)(cross + within);
    }

    // transposed store: scattered writes (fire-and-forget), coalesced scan reads
    for (int c = r; c < C; c += SEG) {
        int cnt = 0;
        #pragma unroll
        for (int j = 0; j < WPB; j++) cnt += whist[j][c];
        g_seg_counts_t[c][blockIdx.x] = cnt;
    }
}

// ---- 3: per-class exclusive scan over segments + bn (coalesced loads) -------
__global__ void k_scan(int nseg, const float* __restrict__ gtp) {
    int c = blockIdx.x;
    int s = threadIdx.x;
    int lane = s & 31, w = s >> 5;

    if (c == 0 && s == 0) g_nact = 0;    // reset before k_compact fills it

    int v = (s < nseg) ? g_seg_counts_t[c][s] : 0;   // consecutive -> coalesced

    int x = v;
    #pragma unroll
    for (int o = 1; o < 32; o <<= 1) {
        int t = __shfl_up_sync(FULLMASK, x, o);
        if (lane >= o) x += t;
    }

    __shared__ int wsum[8];
    __shared__ int woff[8];
    if (lane == 31) wsum[w] = x;
    __syncthreads();
    if (w == 0) {
        int y = (lane < 8) ? wsum[lane] : 0;
        #pragma unroll
        for (int o = 1; o < 8; o <<= 1) {
            int t = __shfl_up_sync(FULLMASK, y, o);
            if (lane >= o) y += t;
        }
        if (lane < 8) woff[lane] = y;
    }
    __syncthreads();

    int incl = x + (w ? woff[w - 1] : 0);
    if (s < nseg) g_seg_off[s][c] = incl - v;
    if (s == SEG - 1) {
        // round half-to-even, matching jnp.round
        g_bn[c] = (int)rintf((float)incl * gtp[c]);
    }
}

// ---- 4: build active-row list (rebal mask) ----------------------------------
__global__ void k_compact(int N) {
    int row = blockIdx.x * SEG + threadIdx.x;
    if (row >= N) return;
    int tgt = g_tm[row];
    bool active = false;
    if (tgt != 0) {
        int rank = g_seg_off[row >> 8][tgt] + (int)g_local[row];
        active = (rank < g_bn[tgt]);
    }
    if (active) {
        unsigned int p = atomicAdd(&g_nact, 1u);
        g_alist[p] = row;
    } else {
        g_ce_u[row] = 0.f;
    }
}

// ---- 5: unsupervised CE for active rows only --------------------------------
__global__ void __launch_bounds__(WPB * 32, 8)
k_su(const float* __restrict__ lsu, int C) {
    int lane = threadIdx.x & 31;
    int w = blockIdx.x * WPB + (threadIdx.x >> 5);
    if (w >= (int)g_nact) return;        // one broadcast load, then exit
    int row = g_alist[w];
    int tgt = g_tm[row];

    const float* rowp = lsu + (size_t)row * C;
    const float4* rp = (const float4*)rowp;
    int n4 = C >> 2;
    int tail = C & 3;
    float tval = __ldg(rowp + tgt);

    float s0 = 0.f, s1 = 0.f;
    #pragma unroll
    for (int u = 0; u < 8; u++) {
        int k = lane + u * 32;
        if (k < n4) {
            float4 c = __ldcs(rp + k);
            s0 += exp2f(c.x * L2E) + exp2f(c.y * L2E);
            s1 += exp2f(c.z * L2E) + exp2f(c.w * L2E);
        }
    }
    if (tail && lane < tail)
        s0 += exp2f(__ldcs(rowp + 4 * n4 + lane) * L2E);
    float s = s0 + s1;

    #pragma unroll
    for (int o = 16; o; o >>= 1) s += __shfl_xor_sync(FULLMASK, s, o);

    if (lane == 0)
        g_ce_u[row] = logf(s) - tval;
}

// ---- 6: deterministic final reduction ---------------------------------------
__global__ void k_reduce(int Bx, int N, float* __restrict__ out) {
    __shared__ float sh[1024];
    __shared__ float lx_s;
    int tid = threadIdx.x;

    float a = 0.f;
    for (int i = tid; i < Bx; i += 1024) a += g_ce_x[i];
    sh[tid] = a;
    __syncthreads();
    for (int o = 512; o; o >>= 1) {
        if (tid < o) sh[tid] += sh[tid + o];
        __syncthreads();
    }
    if (tid == 0) lx_s = sh[0];
    __syncthreads();

    float b = 0.f;
    for (int i = tid; i < N; i += 1024) b += g_ce_u[i];
    sh[tid] = b;
    __syncthreads();
    for (int o = 512; o; o >>= 1) {
        if (tid < o) sh[tid] += sh[tid + o];
        __syncthreads();
    }
    if (tid == 0) {
        float Lx = lx_s / (float)Bx;
        float Lu = sh[0] / (float)N;
        out[0] = Lx + Lu;  // LAMBDA_U = 1.0
        out[1] = Lx;
        out[2] = Lu;
    }
}

// ---------------------------------------------------------------------------
extern "C" void kernel_launch(void* const* d_in, const int* in_sizes, int n_in,
                              void* d_out, int out_size) {
    const float* lx  = (const float*)d_in[0];
    const float* lwu = (const float*)d_in[1];
    const float* lsu = (const float*)d_in[2];
    const int*   tx  = (const int*)d_in[3];
    const float* gtp = (const float*)d_in[4];
    // d_in[5] = t (unused)

    int Bx = in_sizes[3];
    int C  = in_sizes[4];
    int N  = in_sizes[1] / C;
    int nseg = (N + SEG - 1) / SEG;

    float* out = (float*)d_out;

    int rows = N + Bx;
    int blk_rows = (rows + WPB - 1) / WPB;
    int blk_n    = (N + WPB - 1) / WPB;

    k_rows<<<blk_rows, WPB * 32>>>(lwu, lx, tx, C, N, Bx, out + 3);   // 1
    k_seghist_rank<<<nseg, SEG>>>(N, C);                              // 2
    k_scan<<<C, SEG>>>(nseg, gtp);                                    // 3
    k_compact<<<nseg, SEG>>>(N);                                      // 4 <- profiled
    k_su<<<blk_n, WPB * 32>>>(lsu, C);                                // 5
    k_reduce<<<1, 1024>>>(Bx, N, out);                                // 6
}